// round 2
// baseline (speedup 1.0000x reference)
#include <cuda_runtime.h>
#include <cstdint>

#define B_   16
#define F_   256
#define T_   4096
#define L_   128
#define M_   1024
#define D_   128
#define TC_  2048
#define N_   32768          // B*TC

#define OFF_VF  16777216    // B*F*T
#define OFF_IND 25165824    // OFF_VF + B*T*L

// Scratch (device globals — no allocation allowed)
__device__ __align__(16) float g_xqT[2][D_][N_];   // x permuted+transposed: [cb][d][n]
__device__ __align__(16) float g_eT[2][D_][M_];    // codebook transposed:   [cb][d][m]
__device__ __align__(16) float g_cm[2][M_];        // -5*||e_m||^2
__device__ __align__(16) int   g_idx[2][N_];       // argmax indices
__device__ __align__(16) float g_vf[B_ * T_ * L_]; // vq_feat [b][t][l]

// ---------- fp32x2 packed FMA helpers (FFMA2: only reachable via PTX) ----------
__device__ __forceinline__ unsigned long long pkdup(float x) {
    unsigned long long r; unsigned int xi = __float_as_uint(x);
    asm("mov.b64 %0, {%1, %2};" : "=l"(r) : "r"(xi), "r"(xi));
    return r;
}
__device__ __forceinline__ void ffma2(unsigned long long &acc, unsigned long long a,
                                      unsigned long long b) {
    asm("fma.rn.f32x2 %0, %1, %2, %0;" : "+l"(acc) : "l"(a), "l"(b));
}
__device__ __forceinline__ float2 upk(unsigned long long v) {
    unsigned int lo, hi;
    asm("mov.b64 {%0, %1}, %2;" : "=r"(lo), "=r"(hi) : "l"(v));
    float2 r; r.x = __uint_as_float(lo); r.y = __uint_as_float(hi);
    return r;
}

// ---------- Kernel 0: codebook transpose + (-5*||e||^2) ----------
__global__ void k_prep(const float* __restrict__ cb) {
    int i = blockIdx.y;
    int m = blockIdx.x * 128 + threadIdx.x;
    const float* row = cb + (size_t)(i * M_ + m) * D_;
    float s = 0.f;
#pragma unroll 8
    for (int d = 0; d < D_; d++) {
        float e = row[d];
        s += e * e;
        g_eT[i][d][m] = e;
    }
    g_cm[i][m] = -5.0f * s;
}

// ---------- Kernel 1: conv1x1_1 + VQ-layout permute -> g_xqT ----------
// x[b,t,l] = sum_f in[b,f,t] * w1[l,f];  g_xqT[l>>6][(t&1)*64 + (l&63)][b*TC + t/2] = x
__global__ void __launch_bounds__(256, 2) k_conv1(const float* __restrict__ in,
                                                  const float* __restrict__ w1) {
    __shared__ float sm[2 * 32 * 136];
    float* Aw = sm;               // [f][l]  (w1 chunk, transposed)
    float* Bi = sm + 32 * 136;    // [f][t]  (input chunk)
    int tid = threadIdx.x, tx = tid & 15, ty = tid >> 4;
    int b = blockIdx.y, t0 = blockIdx.x << 7;

    unsigned long long acc[8][4];   // rows a = l (ty*8+a), col pairs q over t (tx*8 + 2q{,+1})
#pragma unroll
    for (int a = 0; a < 8; a++)
#pragma unroll
        for (int q = 0; q < 4; q++) acc[a][q] = 0ULL;

    for (int kc = 0; kc < 8; kc++) {
        int f0 = kc << 5;
#pragma unroll
        for (int r = 0; r < 4; r++) {        // w1 chunk [128 l][32 f] -> Aw[f][l]
            int lin = tid + (r << 8);
            int l = lin >> 3, fq = (lin & 7) << 2;
            float4 v = *(const float4*)(w1 + l * F_ + f0 + fq);
            Aw[(fq + 0) * 136 + l] = v.x; Aw[(fq + 1) * 136 + l] = v.y;
            Aw[(fq + 2) * 136 + l] = v.z; Aw[(fq + 3) * 136 + l] = v.w;
        }
#pragma unroll
        for (int r = 0; r < 4; r++) {        // in chunk [32 f][128 t] -> Bi[f][t]
            int lin = tid + (r << 8);
            int f = lin >> 5, tq = (lin & 31) << 2;
            float4 v = *(const float4*)(in + (size_t)(b * F_ + f0 + f) * T_ + t0 + tq);
            *(float4*)(Bi + f * 136 + tq) = v;
        }
        __syncthreads();
#pragma unroll 8
        for (int f = 0; f < 32; f++) {
            float4 a0 = *(const float4*)(Aw + f * 136 + ty * 8);
            float4 a1 = *(const float4*)(Aw + f * 136 + ty * 8 + 4);
            const unsigned long long* bp =
                (const unsigned long long*)(Bi + f * 136 + tx * 8);
            unsigned long long b0 = bp[0], b1 = bp[1], b2 = bp[2], b3 = bp[3];
            unsigned long long ad[8] = {pkdup(a0.x), pkdup(a0.y), pkdup(a0.z), pkdup(a0.w),
                                        pkdup(a1.x), pkdup(a1.y), pkdup(a1.z), pkdup(a1.w)};
#pragma unroll
            for (int a = 0; a < 8; a++) {
                ffma2(acc[a][0], ad[a], b0);
                ffma2(acc[a][1], ad[a], b1);
                ffma2(acc[a][2], ad[a], b2);
                ffma2(acc[a][3], ad[a], b3);
            }
        }
        __syncthreads();
    }

    // Stage through smem (two halves to fit) and write coalesced into g_xqT
    int nb = b * TC_ + (t0 >> 1);
    for (int h = 0; h < 2; h++) {
        if ((tx >> 3) == h) {
#pragma unroll
            for (int a = 0; a < 8; a++)
#pragma unroll
                for (int q = 0; q < 4; q++) {
                    float2 s = upk(acc[a][q]);
                    int tl = ((tx & 7) << 3) + (q << 1);   // local t within half
                    sm[tl * 129 + ty * 8 + a] = s.x;
                    sm[(tl + 1) * 129 + ty * 8 + a] = s.y;
                }
        }
        __syncthreads();
#pragma unroll
        for (int w = 0; w < 32; w++) {
            int e = (w << 8) + tid;          // 8192 elements per half
            int nn = e & 31, rem = e >> 5;
            int cf = rem & 1, l = rem >> 1;
            float v = sm[(2 * nn + cf) * 129 + l];
            int ci = l >> 6, d = (cf << 6) + (l & 63);
            g_xqT[ci][d][nb + h * 32 + nn] = v;
        }
        __syncthreads();
    }
}

// ---------- Kernel 2: distance GEMM + gumbel + row argmax ----------
// score(n,m) = 10*(x_n . e_m) - 5*||e_m||^2 + gumbel[n,m]   (monotone == reference logits+g)
__global__ void __launch_bounds__(256, 2) k_dist(const float* __restrict__ gum) {
    __shared__ float sm[2 * 32 * 136];
    float* Xs = sm;               // [d][n]
    float* Es = sm + 32 * 136;    // [d][m]
    int tid = threadIdx.x, tx = tid & 15, ty = tid >> 4;
    int i = blockIdx.y;
    int nb = blockIdx.x << 7;     // 128 rows per block

    float bestv[8]; int bestm[8];
#pragma unroll
    for (int a = 0; a < 8; a++) { bestv[a] = -3.4e38f; bestm[a] = 0; }

    for (int mc = 0; mc < 8; mc++) {
        int m0 = mc << 7;
        unsigned long long acc[8][4];  // rows a over n (ty*8+a), pairs q over m (tx*8+2q{,+1})
#pragma unroll
        for (int a = 0; a < 8; a++)
#pragma unroll
            for (int q = 0; q < 4; q++) acc[a][q] = 0ULL;

        for (int dc = 0; dc < 4; dc++) {
            int d0 = dc << 5;
#pragma unroll
            for (int r = 0; r < 4; r++) {
                int lin = tid + (r << 8);
                int dd = lin >> 5, rq = (lin & 31) << 2;
                *(float4*)(Xs + dd * 136 + rq) =
                    *(const float4*)(&g_xqT[i][d0 + dd][nb + rq]);
                *(float4*)(Es + dd * 136 + rq) =
                    *(const float4*)(&g_eT[i][d0 + dd][m0 + rq]);
            }
            __syncthreads();
#pragma unroll 8
            for (int dd = 0; dd < 32; dd++) {
                float4 a0 = *(const float4*)(Xs + dd * 136 + ty * 8);
                float4 a1 = *(const float4*)(Xs + dd * 136 + ty * 8 + 4);
                const unsigned long long* bp =
                    (const unsigned long long*)(Es + dd * 136 + tx * 8);
                unsigned long long b0 = bp[0], b1 = bp[1], b2 = bp[2], b3 = bp[3];
                unsigned long long ad[8] = {pkdup(a0.x), pkdup(a0.y), pkdup(a0.z), pkdup(a0.w),
                                            pkdup(a1.x), pkdup(a1.y), pkdup(a1.z), pkdup(a1.w)};
#pragma unroll
                for (int a = 0; a < 8; a++) {
                    ffma2(acc[a][0], ad[a], b0);
                    ffma2(acc[a][1], ad[a], b1);
                    ffma2(acc[a][2], ad[a], b2);
                    ffma2(acc[a][3], ad[a], b3);
                }
            }
            __syncthreads();
        }

        // epilogue: add -5||e||^2 + gumbel, update running argmax
        float4 c0 = *(const float4*)(&g_cm[i][m0 + tx * 8]);
        float4 c1 = *(const float4*)(&g_cm[i][m0 + tx * 8 + 4]);
#pragma unroll
        for (int a = 0; a < 8; a++) {
            const float* gp = gum + ((size_t)i * N_ + nb + ty * 8 + a) * (size_t)M_
                              + m0 + tx * 8;
            float4 g0 = *(const float4*)gp;
            float4 g1 = *(const float4*)(gp + 4);
            float2 s0 = upk(acc[a][0]), s1 = upk(acc[a][1]);
            float2 s2 = upk(acc[a][2]), s3 = upk(acc[a][3]);
            float sc[8] = {10.f * s0.x + c0.x + g0.x, 10.f * s0.y + c0.y + g0.y,
                           10.f * s1.x + c0.z + g0.z, 10.f * s1.y + c0.w + g0.w,
                           10.f * s2.x + c1.x + g1.x, 10.f * s2.y + c1.y + g1.y,
                           10.f * s3.x + c1.z + g1.z, 10.f * s3.y + c1.w + g1.w};
#pragma unroll
            for (int cc = 0; cc < 8; cc++) {
                int m = m0 + tx * 8 + cc;
                if (sc[cc] > bestv[a]) { bestv[a] = sc[cc]; bestm[a] = m; }
            }
        }
    }

    // reduce across the 16 tx lanes (half-warp), keep lowest m on ties
#pragma unroll
    for (int a = 0; a < 8; a++) {
        float v = bestv[a]; int m = bestm[a];
#pragma unroll
        for (int off = 8; off >= 1; off >>= 1) {
            float ov = __shfl_down_sync(0xffffffffu, v, off, 16);
            int   om = __shfl_down_sync(0xffffffffu, m, off, 16);
            if (ov > v || (ov == v && om < m)) { v = ov; m = om; }
        }
        if (tx == 0) g_idx[i][nb + ty * 8 + a] = m;
    }
}

// ---------- Kernel 3: dequantize gather -> g_vf (+ optional d_out vf/inds) ----------
__global__ void k_gather(const float* __restrict__ cb, float* __restrict__ dout,
                         int write_vf, int write_inds) {
    int gt = blockIdx.x * 256 + threadIdx.x;  // 0..2097151  (float4 index of vq_feat)
    int l4 = gt & 31;
    int t = (gt >> 5) & 4095;
    int b = gt >> 17;
    int l = l4 << 2;
    int ci = l >> 6;
    int cf = t & 1;
    int n = b * TC_ + (t >> 1);
    int idx = g_idx[ci][n];
    float4 v = *(const float4*)(cb + (size_t)(ci * M_ + idx) * D_ + (cf << 6) + (l & 63));
    *(float4*)(g_vf + ((size_t)gt << 2)) = v;
    if (write_vf) *(float4*)(dout + OFF_VF + ((size_t)gt << 2)) = v;
    if (write_inds && gt < 65536) {
        int ii = gt & 1, nn = gt >> 1;   // quant_inds[b][tc][k] = [n][k]
        dout[OFF_IND + gt] = (float)g_idx[ii][nn];
    }
}

// ---------- Kernel 4: conv1x1_2 -> out[b][f][t] ----------
__global__ void __launch_bounds__(256, 2) k_conv2(const float* __restrict__ w2,
                                                  float* __restrict__ dout) {
    __shared__ float sm[2 * 32 * 136];
    float* Ws = sm;               // [l][f]
    float* Vs = sm + 32 * 136;    // [l][t]
    int tid = threadIdx.x, tx = tid & 15, ty = tid >> 4;
    int t0 = blockIdx.x << 7;
    int f0 = blockIdx.y << 7;
    int b = blockIdx.z;

    unsigned long long acc[8][4];  // rows a over f, pairs q over t
#pragma unroll
    for (int a = 0; a < 8; a++)
#pragma unroll
        for (int q = 0; q < 4; q++) acc[a][q] = 0ULL;

    for (int lc = 0; lc < 4; lc++) {
        int l0 = lc << 5;
#pragma unroll
        for (int r = 0; r < 4; r++) {
            int lin = tid + (r << 8);
            int ff = lin >> 3, lq = (lin & 7) << 2;
            float4 v = *(const float4*)(w2 + (f0 + ff) * D_ + l0 + lq);
            Ws[(lq + 0) * 136 + ff] = v.x; Ws[(lq + 1) * 136 + ff] = v.y;
            Ws[(lq + 2) * 136 + ff] = v.z; Ws[(lq + 3) * 136 + ff] = v.w;
            int tt = ff;  // same decomposition for vf tile
            float4 u = *(const float4*)(g_vf + (size_t)(b * T_ + t0 + tt) * L_ + l0 + lq);
            Vs[(lq + 0) * 136 + tt] = u.x; Vs[(lq + 1) * 136 + tt] = u.y;
            Vs[(lq + 2) * 136 + tt] = u.z; Vs[(lq + 3) * 136 + tt] = u.w;
        }
        __syncthreads();
#pragma unroll 8
        for (int lw = 0; lw < 32; lw++) {
            float4 a0 = *(const float4*)(Ws + lw * 136 + ty * 8);
            float4 a1 = *(const float4*)(Ws + lw * 136 + ty * 8 + 4);
            const unsigned long long* bp =
                (const unsigned long long*)(Vs + lw * 136 + tx * 8);
            unsigned long long b0 = bp[0], b1 = bp[1], b2 = bp[2], b3 = bp[3];
            unsigned long long ad[8] = {pkdup(a0.x), pkdup(a0.y), pkdup(a0.z), pkdup(a0.w),
                                        pkdup(a1.x), pkdup(a1.y), pkdup(a1.z), pkdup(a1.w)};
#pragma unroll
            for (int a = 0; a < 8; a++) {
                ffma2(acc[a][0], ad[a], b0);
                ffma2(acc[a][1], ad[a], b1);
                ffma2(acc[a][2], ad[a], b2);
                ffma2(acc[a][3], ad[a], b3);
            }
        }
        __syncthreads();
    }

#pragma unroll
    for (int a = 0; a < 8; a++) {
        float2 s0 = upk(acc[a][0]), s1 = upk(acc[a][1]);
        float2 s2 = upk(acc[a][2]), s3 = upk(acc[a][3]);
        float4 o0 = make_float4(s0.x, s0.y, s1.x, s1.y);
        float4 o1 = make_float4(s2.x, s2.y, s3.x, s3.y);
        size_t base = (size_t)(b * F_ + f0 + ty * 8 + a) * T_ + t0 + tx * 8;
        *(float4*)(dout + base) = o0;
        *(float4*)(dout + base + 4) = o1;
    }
}

extern "C" void kernel_launch(void* const* d_in, const int* in_sizes, int n_in,
                              void* d_out, int out_size) {
    const float* in  = (const float*)d_in[0];   // [16,256,4096,1]
    const float* w1  = (const float*)d_in[1];   // [128,256]
    const float* w2  = (const float*)d_in[2];   // [256,128]
    const float* cb  = (const float*)d_in[3];   // [2,1024,128]
    const float* gum = (const float*)d_in[4];   // [2,32768,1024]
    float* dout = (float*)d_out;

    int write_vf   = (out_size >= OFF_VF + B_ * T_ * L_) ? 1 : 0;
    int write_inds = (out_size >= OFF_IND + N_ * 2) ? 1 : 0;

    k_prep<<<dim3(8, 2), 128>>>(cb);
    k_conv1<<<dim3(32, 16), 256>>>(in, w1);
    k_dist<<<dim3(256, 2), 256>>>(gum);
    k_gather<<<8192, 256>>>(cb, dout, write_vf, write_inds);
    k_conv2<<<dim3(32, 2, 16), 256>>>(w2, dout);
}

// round 4
// speedup vs baseline: 1.2589x; 1.2589x over previous
#include <cuda_runtime.h>
#include <cuda_bf16.h>
#include <cstdint>

#define B_   16
#define F_   256
#define T_   4096
#define L_   128
#define M_   1024
#define D_   128
#define TC_  2048
#define N_   32768

#define OFF_VF  16777216
#define OFF_IND 25165824

// device scratch
__device__ __align__(16) __nv_bfloat16 g_xh16[2][N_][D_];
__device__ __align__(16) __nv_bfloat16 g_xl16[2][N_][D_];
__device__ __align__(16) float         g_xf  [2][N_][D_];
__device__ __align__(16) __nv_bfloat16 g_eh16[2][M_][D_];
__device__ __align__(16) __nv_bfloat16 g_el16[2][M_][D_];
__device__ __align__(16) float g_cm[2][M_];
__device__ __align__(16) int   g_idx[2][N_];
__device__ __align__(16) float g_vf[B_ * T_ * L_];
__device__ int   g_fixc;
__device__ int   g_fixn[N_ * 2];

// ---- fp32x2 helpers (conv kernels) ----
__device__ __forceinline__ unsigned long long pkdup(float x) {
    unsigned long long r; unsigned int xi = __float_as_uint(x);
    asm("mov.b64 %0, {%1, %2};" : "=l"(r) : "r"(xi), "r"(xi));
    return r;
}
__device__ __forceinline__ void ffma2(unsigned long long &acc, unsigned long long a,
                                      unsigned long long b) {
    asm("fma.rn.f32x2 %0, %1, %2, %0;" : "+l"(acc) : "l"(a), "l"(b));
}
__device__ __forceinline__ float2 upk(unsigned long long v) {
    unsigned int lo, hi;
    asm("mov.b64 {%0, %1}, %2;" : "=r"(lo), "=r"(hi) : "l"(v));
    float2 r; r.x = __uint_as_float(lo); r.y = __uint_as_float(hi);
    return r;
}

// ---- mma helpers (baseline PTX, no sm_103a-gated instructions) ----
__device__ __forceinline__ uint32_t sm_u32(const void* p) {
    uint32_t a;
    asm("{ .reg .u64 t; cvta.to.shared.u64 t, %1; cvt.u32.u64 %0, t; }" : "=r"(a) : "l"(p));
    return a;
}
__device__ __forceinline__ void ldsm4(uint32_t& r0, uint32_t& r1, uint32_t& r2, uint32_t& r3,
                                      uint32_t a) {
    asm volatile("ldmatrix.sync.aligned.m8n8.x4.shared.b16 {%0,%1,%2,%3}, [%4];"
                 : "=r"(r0), "=r"(r1), "=r"(r2), "=r"(r3) : "r"(a));
}
__device__ __forceinline__ void mma16816(float* c, uint32_t a0, uint32_t a1, uint32_t a2,
                                         uint32_t a3, uint32_t b0, uint32_t b1) {
    asm volatile(
        "mma.sync.aligned.m16n8k16.row.col.f32.bf16.bf16.f32 "
        "{%0,%1,%2,%3},{%4,%5,%6,%7},{%8,%9},{%0,%1,%2,%3};"
        : "+f"(c[0]), "+f"(c[1]), "+f"(c[2]), "+f"(c[3])
        : "r"(a0), "r"(a1), "r"(a2), "r"(a3), "r"(b0), "r"(b1));
}

// ---------- k_prep: codebook bf16 hi/lo split + cm ----------
__global__ void k_prep(const float* __restrict__ cb) {
    if (blockIdx.x == 0 && blockIdx.y == 0 && threadIdx.x == 0) g_fixc = 0;
    int w = threadIdx.x >> 5, lane = threadIdx.x & 31;
    int i = blockIdx.y, m = blockIdx.x * 8 + w;
    const float* row = cb + (size_t)(i * M_ + m) * D_;
    float4 v = *(const float4*)(row + lane * 4);
    float s = v.x * v.x + v.y * v.y + v.z * v.z + v.w * v.w;
    float vv[4] = {v.x, v.y, v.z, v.w};
#pragma unroll
    for (int j = 0; j < 4; j++) {
        __nv_bfloat16 hb = __float2bfloat16(vv[j]);
        g_eh16[i][m][lane * 4 + j] = hb;
        g_el16[i][m][lane * 4 + j] = __float2bfloat16(vv[j] - __bfloat162float(hb));
    }
#pragma unroll
    for (int o = 16; o >= 1; o >>= 1) s += __shfl_xor_sync(0xffffffffu, s, o);
    if (lane == 0) g_cm[i][m] = -5.0f * s;
}

// ---------- k_conv1: conv1x1_1 + bf16 split -> g_xh16/g_xl16/g_xf [cb][n][d] ----------
__global__ void __launch_bounds__(256, 2) k_conv1(const float* __restrict__ in,
                                                  const float* __restrict__ w1) {
    __shared__ float sm[2 * 32 * 136];
    float* Aw = sm;
    float* Bi = sm + 32 * 136;
    int tid = threadIdx.x, tx = tid & 15, ty = tid >> 4;
    int b = blockIdx.y, t0 = blockIdx.x << 7;

    unsigned long long acc[8][4];
#pragma unroll
    for (int a = 0; a < 8; a++)
#pragma unroll
        for (int q = 0; q < 4; q++) acc[a][q] = 0ULL;

    for (int kc = 0; kc < 8; kc++) {
        int f0 = kc << 5;
#pragma unroll
        for (int r = 0; r < 4; r++) {
            int lin = tid + (r << 8);
            int l = lin >> 3, fq = (lin & 7) << 2;
            float4 v = *(const float4*)(w1 + l * F_ + f0 + fq);
            Aw[(fq + 0) * 136 + l] = v.x; Aw[(fq + 1) * 136 + l] = v.y;
            Aw[(fq + 2) * 136 + l] = v.z; Aw[(fq + 3) * 136 + l] = v.w;
        }
#pragma unroll
        for (int r = 0; r < 4; r++) {
            int lin = tid + (r << 8);
            int f = lin >> 5, tq = (lin & 31) << 2;
            float4 v = *(const float4*)(in + (size_t)(b * F_ + f0 + f) * T_ + t0 + tq);
            *(float4*)(Bi + f * 136 + tq) = v;
        }
        __syncthreads();
#pragma unroll 8
        for (int f = 0; f < 32; f++) {
            float4 a0 = *(const float4*)(Aw + f * 136 + ty * 8);
            float4 a1 = *(const float4*)(Aw + f * 136 + ty * 8 + 4);
            const unsigned long long* bp = (const unsigned long long*)(Bi + f * 136 + tx * 8);
            unsigned long long b0 = bp[0], b1 = bp[1], b2 = bp[2], b3 = bp[3];
            unsigned long long ad[8] = {pkdup(a0.x), pkdup(a0.y), pkdup(a0.z), pkdup(a0.w),
                                        pkdup(a1.x), pkdup(a1.y), pkdup(a1.z), pkdup(a1.w)};
#pragma unroll
            for (int a = 0; a < 8; a++) {
                ffma2(acc[a][0], ad[a], b0);
                ffma2(acc[a][1], ad[a], b1);
                ffma2(acc[a][2], ad[a], b2);
                ffma2(acc[a][3], ad[a], b3);
            }
        }
        __syncthreads();
    }

    int nb = b * TC_ + (t0 >> 1);
    for (int h = 0; h < 2; h++) {
        if ((tx >> 3) == h) {
#pragma unroll
            for (int a = 0; a < 8; a++)
#pragma unroll
                for (int q = 0; q < 4; q++) {
                    float2 s = upk(acc[a][q]);
                    int tl = ((tx & 7) << 3) + (q << 1);
                    sm[tl * 129 + ty * 8 + a] = s.x;
                    sm[(tl + 1) * 129 + ty * 8 + a] = s.y;
                }
        }
        __syncthreads();
#pragma unroll
        for (int w = 0; w < 32; w++) {
            int e = (w << 8) + tid;
            int d = e & 127, cbb = (e >> 7) & 1, nn = e >> 8;
            float v = sm[(2 * nn + (d >> 6)) * 129 + (cbb << 6) + (d & 63)];
            int n = nb + h * 32 + nn;
            __nv_bfloat16 hb = __float2bfloat16(v);
            g_xh16[cbb][n][d] = hb;
            g_xl16[cbb][n][d] = __float2bfloat16(v - __bfloat162float(hb));
            g_xf[cbb][n][d] = v;
        }
        __syncthreads();
    }
}

// ---------- k_dist_mma: bf16x3 mma.sync distance GEMM + gumbel + argmax ----------
// smem: Xh [128][128]bf16 @0 (32K), Xl @32768, E @65536 (32K), cms @98304 (4K), red @102400
#define DSM_TOT 103936

__device__ __forceinline__ void do_pass(uint32_t sX, uint32_t sE, int lane, int wr, int wc,
                                        float c[2][8][4]) {
#pragma unroll
    for (int ks = 0; ks < 8; ks++) {
        uint32_t a[2][4];
#pragma unroll
        for (int tm = 0; tm < 2; tm++) {
            int rowA = wr * 32 + tm * 16 + (lane & 15);
            int koA = ks * 2 + (lane >> 4);
            ldsm4(a[tm][0], a[tm][1], a[tm][2], a[tm][3],
                  sX + rowA * 256 + ((koA ^ (rowA & 7)) << 4));
        }
#pragma unroll
        for (int pr = 0; pr < 4; pr++) {
            int nB = wc * 64 + pr * 16 + (lane & 7) + ((lane >> 4) << 3);
            int koB = ks * 2 + ((lane >> 3) & 1);
            uint32_t b0, b1, b2, b3;
            ldsm4(b0, b1, b2, b3, sE + nB * 256 + ((koB ^ (nB & 7)) << 4));
            mma16816(c[0][pr * 2],     a[0][0], a[0][1], a[0][2], a[0][3], b0, b1);
            mma16816(c[0][pr * 2 + 1], a[0][0], a[0][1], a[0][2], a[0][3], b2, b3);
            mma16816(c[1][pr * 2],     a[1][0], a[1][1], a[1][2], a[1][3], b0, b1);
            mma16816(c[1][pr * 2 + 1], a[1][0], a[1][1], a[1][2], a[1][3], b2, b3);
        }
    }
}

__global__ void __launch_bounds__(256, 1) k_dist_mma(const float* __restrict__ gum) {
    extern __shared__ char smem[];
    float* cms = (float*)(smem + 98304);
    float* redv = (float*)(smem + 102400);
    float* redb = redv + 128;
    int*   redi = (int*)(redb + 128);
    uint32_t sXh = sm_u32(smem), sXl = sXh + 32768, sE = sXh + 65536;

    int tid = threadIdx.x, lane = tid & 31, wid = tid >> 5;
    int wr = wid >> 1, wc = wid & 1;
    int cbi = blockIdx.y, n0 = blockIdx.x << 7;

    // stage X (both planes) swizzled + cms
#pragma unroll
    for (int i = 0; i < 8; i++) {
        int lin = tid + (i << 8);
        int row = lin >> 4, ko = lin & 15;
        uint32_t off = row * 256 + ((ko ^ (row & 7)) << 4);
        *(uint4*)(smem + off)         = *(const uint4*)(&g_xh16[cbi][n0 + row][ko * 8]);
        *(uint4*)(smem + 32768 + off) = *(const uint4*)(&g_xl16[cbi][n0 + row][ko * 8]);
    }
    *(float4*)(&cms[tid * 4]) = *(const float4*)(&g_cm[cbi][tid * 4]);

    float best[4], b2[4]; int bm[4];
#pragma unroll
    for (int s = 0; s < 4; s++) { best[s] = -3.4e38f; b2[s] = -3.4e38f; bm[s] = 0; }

#pragma unroll 1
    for (int mc = 0; mc < 8; mc++) {
        float c[2][8][4];
#pragma unroll
        for (int tm = 0; tm < 2; tm++)
#pragma unroll
            for (int tn = 0; tn < 8; tn++)
#pragma unroll
                for (int q = 0; q < 4; q++) c[tm][tn][q] = 0.f;

        const __nv_bfloat16* ehp = &g_eh16[cbi][mc << 7][0];
        const __nv_bfloat16* elp = &g_el16[cbi][mc << 7][0];

        __syncthreads();
#pragma unroll
        for (int i = 0; i < 8; i++) {
            int lin = tid + (i << 8);
            int row = lin >> 4, ko = lin & 15;
            *(uint4*)(smem + 65536 + row * 256 + ((ko ^ (row & 7)) << 4)) =
                *(const uint4*)(ehp + row * 128 + ko * 8);
        }
        __syncthreads();
        do_pass(sXh, sE, lane, wr, wc, c);   // Xh * Eh
        do_pass(sXl, sE, lane, wr, wc, c);   // Xl * Eh
        __syncthreads();
#pragma unroll
        for (int i = 0; i < 8; i++) {
            int lin = tid + (i << 8);
            int row = lin >> 4, ko = lin & 15;
            *(uint4*)(smem + 65536 + row * 256 + ((ko ^ (row & 7)) << 4)) =
                *(const uint4*)(elp + row * 128 + ko * 8);
        }
        __syncthreads();
        do_pass(sXh, sE, lane, wr, wc, c);   // Xh * El

        // epilogue: +cm +gumbel, running top-2 argmax
        int colbase = (mc << 7) + wc * 64 + ((lane & 3) << 1);
#pragma unroll
        for (int tm = 0; tm < 2; tm++) {
            int r0 = n0 + wr * 32 + tm * 16 + (lane >> 2);
            const float* gr0 = gum + ((size_t)cbi * N_ + r0) * (size_t)M_;
            const float* gr1 = gr0 + (size_t)8 * M_;
#pragma unroll
            for (int tn = 0; tn < 8; tn++) {
                int col = colbase + tn * 8;
                float cm0 = cms[col], cm1 = cms[col + 1];
                float2 ga = *(const float2*)(gr0 + col);
                float2 gb = *(const float2*)(gr1 + col);
                float* cc = c[tm][tn];
                float v0 = fmaf(10.f, cc[0], cm0 + ga.x);
                float v1 = fmaf(10.f, cc[1], cm1 + ga.y);
                float v2 = fmaf(10.f, cc[2], cm0 + gb.x);
                float v3 = fmaf(10.f, cc[3], cm1 + gb.y);
                int s0 = tm * 2, s1 = tm * 2 + 1;
                if (v0 > best[s0]) { b2[s0] = best[s0]; best[s0] = v0; bm[s0] = col; }
                else if (v0 > b2[s0]) b2[s0] = v0;
                if (v1 > best[s0]) { b2[s0] = best[s0]; best[s0] = v1; bm[s0] = col + 1; }
                else if (v1 > b2[s0]) b2[s0] = v1;
                if (v2 > best[s1]) { b2[s1] = best[s1]; best[s1] = v2; bm[s1] = col; }
                else if (v2 > b2[s1]) b2[s1] = v2;
                if (v3 > best[s1]) { b2[s1] = best[s1]; best[s1] = v3; bm[s1] = col + 1; }
                else if (v3 > b2[s1]) b2[s1] = v3;
            }
        }
    }

    // quad reduce (lanes sharing the same rows)
#pragma unroll
    for (int s = 0; s < 4; s++) {
#pragma unroll
        for (int off = 1; off <= 2; off <<= 1) {
            float ov = __shfl_xor_sync(0xffffffffu, best[s], off);
            float o2 = __shfl_xor_sync(0xffffffffu, b2[s], off);
            int om = __shfl_xor_sync(0xffffffffu, bm[s], off);
            if (ov > best[s]) { b2[s] = fmaxf(best[s], o2); best[s] = ov; bm[s] = om; }
            else if (ov == best[s]) { b2[s] = best[s]; if (om < bm[s]) bm[s] = om; }
            else b2[s] = fmaxf(b2[s], fmaxf(ov, o2));
        }
    }
    __syncthreads();
    if (wc == 0 && (lane & 3) == 0) {
#pragma unroll
        for (int s = 0; s < 4; s++) {
            int lr = wr * 32 + (s >> 1) * 16 + ((s & 1) << 3) + (lane >> 2);
            redv[lr] = best[s]; redb[lr] = b2[s]; redi[lr] = bm[s];
        }
    }
    __syncthreads();
    if (wc == 1 && (lane & 3) == 0) {
#pragma unroll
        for (int s = 0; s < 4; s++) {
            int lr = wr * 32 + (s >> 1) * 16 + ((s & 1) << 3) + (lane >> 2);
            float ov = redv[lr], o2 = redb[lr]; int om = redi[lr];
            if (ov > best[s]) { b2[s] = fmaxf(best[s], o2); best[s] = ov; bm[s] = om; }
            else if (ov == best[s]) { b2[s] = best[s]; if (om < bm[s]) bm[s] = om; }
            else b2[s] = fmaxf(b2[s], fmaxf(ov, o2));
            int n = n0 + lr;
            g_idx[cbi][n] = bm[s];
            if (best[s] - b2[s] < 2e-2f) {
                int k = atomicAdd(&g_fixc, 1);
                g_fixn[k] = (cbi << 15) | n;
            }
        }
    }
}

// ---------- k_fix: exact fp32 rescore for small-margin rows ----------
__global__ void k_fix(const float* __restrict__ cb, const float* __restrict__ gum) {
    __shared__ float xs[128];
    __shared__ float rv[256];
    __shared__ int ri[256];
    int nfix = g_fixc;
    int tid = threadIdx.x;
    for (int it = blockIdx.x; it < nfix; it += gridDim.x) {
        int row = g_fixn[it];
        int cbi = row >> 15, n = row & 32767;
        if (tid < 32)
            *(float4*)&xs[tid * 4] = *(const float4*)(&g_xf[cbi][n][tid * 4]);
        __syncthreads();
        float best = -3.4e38f; int bmv = 0;
        for (int m = tid; m < M_; m += 256) {
            const float* e = cb + (size_t)(cbi * M_ + m) * D_;
            float s = 0.f;
#pragma unroll 8
            for (int d = 0; d < 128; d++) s += xs[d] * e[d];
            float sc = 10.f * s + g_cm[cbi][m]
                     + gum[((size_t)cbi * N_ + n) * (size_t)M_ + m];
            if (sc > best) { best = sc; bmv = m; }
        }
        rv[tid] = best; ri[tid] = bmv;
        __syncthreads();
        for (int s2 = 128; s2 >= 1; s2 >>= 1) {
            if (tid < s2) {
                if (rv[tid + s2] > rv[tid] ||
                    (rv[tid + s2] == rv[tid] && ri[tid + s2] < ri[tid])) {
                    rv[tid] = rv[tid + s2]; ri[tid] = ri[tid + s2];
                }
            }
            __syncthreads();
        }
        if (tid == 0) g_idx[cbi][n] = ri[0];
        __syncthreads();
    }
}

// ---------- k_gather ----------
__global__ void k_gather(const float* __restrict__ cb, float* __restrict__ dout,
                         int write_vf, int write_inds) {
    int gt = blockIdx.x * 256 + threadIdx.x;
    int l4 = gt & 31;
    int t = (gt >> 5) & 4095;
    int b = gt >> 17;
    int l = l4 << 2;
    int ci = l >> 6;
    int cf = t & 1;
    int n = b * TC_ + (t >> 1);
    int idx = g_idx[ci][n];
    float4 v = *(const float4*)(cb + (size_t)(ci * M_ + idx) * D_ + (cf << 6) + (l & 63));
    *(float4*)(g_vf + ((size_t)gt << 2)) = v;
    if (write_vf) *(float4*)(dout + OFF_VF + ((size_t)gt << 2)) = v;
    if (write_inds && gt < 65536) {
        int ii = gt & 1, nn = gt >> 1;
        dout[OFF_IND + gt] = (float)g_idx[ii][nn];
    }
}

// ---------- k_conv2 ----------
__global__ void __launch_bounds__(256, 2) k_conv2(const float* __restrict__ w2,
                                                  float* __restrict__ dout) {
    __shared__ float sm[2 * 32 * 136];
    float* Ws = sm;
    float* Vs = sm + 32 * 136;
    int tid = threadIdx.x, tx = tid & 15, ty = tid >> 4;
    int t0 = blockIdx.x << 7;
    int f0 = blockIdx.y << 7;
    int b = blockIdx.z;

    unsigned long long acc[8][4];
#pragma unroll
    for (int a = 0; a < 8; a++)
#pragma unroll
        for (int q = 0; q < 4; q++) acc[a][q] = 0ULL;

    for (int lc = 0; lc < 4; lc++) {
        int l0 = lc << 5;
#pragma unroll
        for (int r = 0; r < 4; r++) {
            int lin = tid + (r << 8);
            int ff = lin >> 3, lq = (lin & 7) << 2;
            float4 v = *(const float4*)(w2 + (f0 + ff) * D_ + l0 + lq);
            Ws[(lq + 0) * 136 + ff] = v.x; Ws[(lq + 1) * 136 + ff] = v.y;
            Ws[(lq + 2) * 136 + ff] = v.z; Ws[(lq + 3) * 136 + ff] = v.w;
            int tt = ff;
            float4 u = *(const float4*)(g_vf + (size_t)(b * T_ + t0 + tt) * L_ + l0 + lq);
            Vs[(lq + 0) * 136 + tt] = u.x; Vs[(lq + 1) * 136 + tt] = u.y;
            Vs[(lq + 2) * 136 + tt] = u.z; Vs[(lq + 3) * 136 + tt] = u.w;
        }
        __syncthreads();
#pragma unroll 8
        for (int lw = 0; lw < 32; lw++) {
            float4 a0 = *(const float4*)(Ws + lw * 136 + ty * 8);
            float4 a1 = *(const float4*)(Ws + lw * 136 + ty * 8 + 4);
            const unsigned long long* bp = (const unsigned long long*)(Vs + lw * 136 + tx * 8);
            unsigned long long b0 = bp[0], b1 = bp[1], b2 = bp[2], b3 = bp[3];
            unsigned long long ad[8] = {pkdup(a0.x), pkdup(a0.y), pkdup(a0.z), pkdup(a0.w),
                                        pkdup(a1.x), pkdup(a1.y), pkdup(a1.z), pkdup(a1.w)};
#pragma unroll
            for (int a = 0; a < 8; a++) {
                ffma2(acc[a][0], ad[a], b0);
                ffma2(acc[a][1], ad[a], b1);
                ffma2(acc[a][2], ad[a], b2);
                ffma2(acc[a][3], ad[a], b3);
            }
        }
        __syncthreads();
    }

#pragma unroll
    for (int a = 0; a < 8; a++) {
        float2 s0 = upk(acc[a][0]), s1 = upk(acc[a][1]);
        float2 s2 = upk(acc[a][2]), s3 = upk(acc[a][3]);
        float4 o0 = make_float4(s0.x, s0.y, s1.x, s1.y);
        float4 o1 = make_float4(s2.x, s2.y, s3.x, s3.y);
        size_t base = (size_t)(b * F_ + f0 + ty * 8 + a) * T_ + t0 + tx * 8;
        *(float4*)(dout + base) = o0;
        *(float4*)(dout + base + 4) = o1;
    }
}

extern "C" void kernel_launch(void* const* d_in, const int* in_sizes, int n_in,
                              void* d_out, int out_size) {
    const float* in  = (const float*)d_in[0];
    const float* w1  = (const float*)d_in[1];
    const float* w2  = (const float*)d_in[2];
    const float* cb  = (const float*)d_in[3];
    const float* gum = (const float*)d_in[4];
    float* dout = (float*)d_out;

    int write_vf   = (out_size >= OFF_VF + B_ * T_ * L_) ? 1 : 0;
    int write_inds = (out_size >= OFF_IND + N_ * 2) ? 1 : 0;

    cudaFuncSetAttribute(k_dist_mma, cudaFuncAttributeMaxDynamicSharedMemorySize, DSM_TOT);

    k_prep<<<dim3(128, 2), 256>>>(cb);
    k_conv1<<<dim3(32, 16), 256>>>(in, w1);
    k_dist_mma<<<dim3(256, 2), 256, DSM_TOT>>>(gum);
    k_fix<<<256, 256>>>(cb, gum);
    k_gather<<<8192, 256>>>(cb, dout, write_vf, write_inds);
    k_conv2<<<dim3(32, 2, 16), 256>>>(w2, dout);
}